// round 16
// baseline (speedup 1.0000x reference)
#include <cuda_runtime.h>
#include <cuda_fp16.h>
#include <cstdint>
#include <cstddef>

// ---------------- problem dims (fixed by the dataset instance) ----------------
#define BLOCK   128
#define EMBED   4096
#define HIDDEN  16384
#define OUTD    4096
#define NZB     32
#define MACT    (NZB * BLOCK)   // 4096 active rows

// ---------------- scratch (device globals: allocation-free rule) -------------
__device__ __half d_g  [(size_t)MACT   * EMBED ];  // gathered activations fp16 [M,K]
__device__ __half d_w1t[(size_t)HIDDEN * EMBED ];  // fc1^T fp16 [N=HIDDEN, K=EMBED]
__device__ __half d_w2t[(size_t)OUTD   * HIDDEN];  // fc2^T fp16 [N=OUTD,   K=HIDDEN]
__device__ __half d_h  [(size_t)MACT   * HIDDEN];  // hidden fp16 [M,K2]
__device__ float  d_part[(size_t)2 * MACT * OUTD]; // GEMM2 split-K partials
__device__ int    d_map[64];                       // block -> active slot (-1 = inactive)

// ---- side stream + fork/join events: created ONCE at static-init (pre-capture,
// pre-checkpoint; no device allocation during kernel_launch itself) ------------
struct OverlapRes {
    cudaStream_t s1;
    cudaEvent_t  e_fork, e_join;
    OverlapRes() {
        cudaStreamCreateWithFlags(&s1, cudaStreamNonBlocking);
        cudaEventCreateWithFlags(&e_fork, cudaEventDisableTiming);
        cudaEventCreateWithFlags(&e_join, cudaEventDisableTiming);
    }
};
static OverlapRes g_ov;

// ---------------- PTX helpers (all portable, sm_80-level) ---------------------
__device__ __forceinline__ uint32_t smem_u32(const void* p) {
    uint32_t a;
    asm("{ .reg .u64 t; cvta.to.shared.u64 t, %1; cvt.u32.u64 %0, t; }" : "=r"(a) : "l"(p));
    return a;
}
__device__ __forceinline__ void cp16(uint32_t dst, const void* src) {
    asm volatile("cp.async.cg.shared.global [%0], [%1], 16;" :: "r"(dst), "l"(src) : "memory");
}
#define CP_COMMIT()  asm volatile("cp.async.commit_group;" ::: "memory")
#define CP_WAIT1()   asm volatile("cp.async.wait_group 1;" ::: "memory")
#define SW128(o) ((o) ^ (((o) >> 3) & 0x70))

__device__ __forceinline__ void ldsm_x4(uint32_t* r, uint32_t addr) {
    asm volatile("ldmatrix.sync.aligned.m8n8.x4.shared.b16 {%0,%1,%2,%3}, [%4];"
                 : "=r"(r[0]), "=r"(r[1]), "=r"(r[2]), "=r"(r[3]) : "r"(addr));
}
__device__ __forceinline__ void ldsm_x2(uint32_t* r, uint32_t addr) {
    asm volatile("ldmatrix.sync.aligned.m8n8.x2.shared.b16 {%0,%1}, [%2];"
                 : "=r"(r[0]), "=r"(r[1]) : "r"(addr));
}
__device__ __forceinline__ void mma16816(float* c, const uint32_t* a, const uint32_t* b) {
    asm volatile(
        "mma.sync.aligned.m16n8k16.row.col.f32.f16.f16.f32 "
        "{%0,%1,%2,%3}, {%4,%5,%6,%7}, {%8,%9}, {%0,%1,%2,%3};"
        : "+f"(c[0]), "+f"(c[1]), "+f"(c[2]), "+f"(c[3])
        : "r"(a[0]), "r"(a[1]), "r"(a[2]), "r"(a[3]), "r"(b[0]), "r"(b[1]));
}

// ---------------- conversion / plumbing kernels -------------------------------
__global__ void gather_convert(const float* __restrict__ x, const int* __restrict__ nz,
                               __half* __restrict__ g) {
    size_t idx  = (size_t)blockIdx.x * blockDim.x + threadIdx.x;  // over MACT*EMBED/4
    int    row  = (int)(idx >> 10);            // EMBED/4 = 1024 float4 per row
    int    col4 = (int)(idx & 1023);
    int    blk  = row >> 7;
    int    srow = nz[blk] * BLOCK + (row & 127);
    float4 v = reinterpret_cast<const float4*>(x)[(size_t)srow * (EMBED / 4) + col4];
    __half2* dst = reinterpret_cast<__half2*>(g + (size_t)row * EMBED + (size_t)col4 * 4);
    dst[0] = __floats2half2_rn(v.x, v.y);
    dst[1] = __floats2half2_rn(v.z, v.w);
}

// in [R,C] fp32 row-major -> out [C,R] fp16 row-major.
// 64(r) x 32(c) tile; writes are __half2 per lane -> full 128B transactions.
__global__ void transpose_convert(const float* __restrict__ in, __half* __restrict__ out,
                                  int R, int C) {
    __shared__ float tile[64][33];
    int c0 = blockIdx.x * 32, r0 = blockIdx.y * 64;
    int tx = threadIdx.x, ty = threadIdx.y;  // (32,8)
#pragma unroll
    for (int j = 0; j < 8; j++) {
        int row = ty + j * 8;                // 0..63
        tile[row][tx] = in[(size_t)(r0 + row) * C + c0 + tx];
    }
    __syncthreads();
#pragma unroll
    for (int i = 0; i < 4; i++) {
        int cc = ty + i * 8;                 // 0..31
        __half2 h = __floats2half2_rn(tile[2 * tx][cc], tile[2 * tx + 1][cc]);
        *reinterpret_cast<__half2*>(out + (size_t)(c0 + cc) * R + r0 + 2 * tx) = h;
    }
}

// block -> slot inverse map (single 64-thread block)
__global__ void build_map(const int* __restrict__ nz) {
    int t = threadIdx.x;
    if (t < 64) d_map[t] = -1;
    __syncthreads();
    if (t < 32) d_map[nz[t]] = t;
}

// full-output pass: active blocks = p0 + p1, inactive blocks = 0 (replaces memset)
__global__ void reduce_scatter_all(const float* __restrict__ part,
                                   float* __restrict__ out) {
    size_t idx  = (size_t)blockIdx.x * blockDim.x + threadIdx.x;  // over 8192*1024
    int    row  = (int)(idx >> 10);            // 0..8191
    int    col4 = (int)(idx & 1023);
    const int slot = d_map[row >> 7];
    float4 v = make_float4(0.f, 0.f, 0.f, 0.f);
    if (slot >= 0) {
        const int srow = slot * BLOCK + (row & 127);
        const float4* p0 = reinterpret_cast<const float4*>(part);
        const float4* p1 = p0 + (size_t)MACT * (OUTD / 4);
        const size_t o = (size_t)srow * (OUTD / 4) + col4;
        float4 a = p0[o], b = p1[o];
        v = make_float4(a.x + b.x, a.y + b.y, a.z + b.z, a.w + b.w);
    }
    reinterpret_cast<float4*>(out)[(size_t)row * (OUTD / 4) + col4] = v;
}

// ---------------- HMMA GEMM (R15, frozen) -------------------------------------
// C[m,n] = sum_k A[m,k]*B[n,k]; operands fp16 K-major with row stride LDA.
// CTA 128x256, warp tile 64x64 (8 warps, 2m x 4n), BK=64, 4-stage cp.async,
// m-fast grid; deferred next-stage issue (after ks0 MMAs). SPLITZ: blockIdx.z
// selects a K-half + a private fp32 partial plane (deterministic split-K).
constexpr int BM = 128, BN = 256, BK = 64, STAGES = 4;
constexpr uint32_t ABYTES      = BM * BK * 2;           // 16384
constexpr uint32_t BBYTES      = BN * BK * 2;           // 32768
constexpr uint32_t STAGE_BYTES = ABYTES + BBYTES;       // 49152
constexpr uint32_t SMEM_DYN    = STAGES * STAGE_BYTES;  // 196608

__device__ __forceinline__ void load_frag_a(uint32_t (&a)[4][4], uint32_t sA,
                                            int wm, int lane, int ks) {
#pragma unroll
    for (int i = 0; i < 4; i++) {
        const uint32_t r  = (uint32_t)(wm * 64 + i * 16 + (lane & 15));
        const uint32_t cb = (uint32_t)(ks * 32 + ((lane >> 4) << 4));
        ldsm_x4(a[i], sA + SW128(r * 128 + cb));
    }
}
__device__ __forceinline__ void load_frag_b(uint32_t (&b)[8][2], uint32_t sB,
                                            int wn, int lane, int ks) {
#pragma unroll
    for (int j = 0; j < 8; j++) {
        const uint32_t r  = (uint32_t)(wn * 64 + j * 8 + (lane & 7));
        const uint32_t cb = (uint32_t)(ks * 32 + (((lane >> 3) & 1) << 4));
        ldsm_x2(b[j], sB + SW128(r * 128 + cb));
    }
}

template <int KTOT, int LDA, int LDC, bool F32OUT, bool SPLITZ>
__global__ void __launch_bounds__(256, 1)
gemm_f16(const __half* __restrict__ A, const __half* __restrict__ B,
         void* __restrict__ C) {
    extern __shared__ char smem[];
    const uint32_t sb = smem_u32(smem);
    const int tid  = threadIdx.x;
    const int lane = tid & 31, wid = tid >> 5;
    const int wm = wid >> 2, wn = wid & 3;             // 2m x 4n warps, 64x64 tiles
    const int m0 = blockIdx.x * BM, n0 = blockIdx.y * BN;   // m-fast grid
    constexpr int KIT = KTOT / BK;

    if (SPLITZ) {                                      // K-half + partial plane
        const size_t koff = (size_t)blockIdx.z * KTOT;
        A += koff;  B += koff;
        C = (void*)((float*)C + (size_t)blockIdx.z * MACT * LDC);
    }

    // cp.async: stage = 384 rows x 128B (rows 0-127 = A, 128-383 = B).
    // thread t owns chunk (t&7) of rows (t>>3) + 32p; p 0-3 -> A, p 0-7 -> B.
    const int rb = tid >> 3;                 // base row 0..31
    const int chb = (tid & 7) * 16;          // byte chunk within 128B row
    const char* gAt = (const char*)(A + (size_t)(m0 + rb) * LDA) + chb;
    const char* gBt = (const char*)(B + (size_t)(n0 + rb) * LDA) + chb;
    const size_t rstep = (size_t)32 * LDA * 2;   // 32 rows in bytes

    float acc[4][8][4];
#pragma unroll
    for (int i = 0; i < 4; i++)
#pragma unroll
        for (int j = 0; j < 8; j++)
#pragma unroll
            for (int q = 0; q < 4; q++) acc[i][j][q] = 0.f;

    // prologue: fill stages 0..2 (3 commits)
#pragma unroll
    for (int s = 0; s < STAGES - 1; s++) {
        const uint32_t st = sb + (uint32_t)s * STAGE_BYTES;
        const size_t ko = (size_t)s * (BK * 2);
#pragma unroll
        for (int p = 0; p < 4; p++)
            cp16(st + SW128((uint32_t)((rb + 32 * p) * 128 + chb)),
                 gAt + ko + (size_t)p * rstep);
#pragma unroll
        for (int p = 0; p < 8; p++)
            cp16(st + ABYTES + SW128((uint32_t)((rb + 32 * p) * 128 + chb)),
                 gBt + ko + (size_t)p * rstep);
        CP_COMMIT();
    }

    uint32_t af[2][4][4], bf[2][8][2];   // double-buffered fragments

    for (int it = 0; it < KIT; it++) {
        // stages <= it+1 resident after this wait (3+it committed, <=1 pending)
        CP_WAIT1();
        __syncthreads();

        const uint32_t sA  = sb + (uint32_t)(it & (STAGES - 1)) * STAGE_BYTES;
        const uint32_t sBs = sA + ABYTES;

        if (it == 0) {             // prime buffer 0 (later iters arrive pre-loaded)
            load_frag_a(af[0], sA, wm, lane, 0);
            load_frag_b(bf[0], sBs, wn, lane, 0);
        }

        // ---- ks = 0: restart tensor pipe immediately (frags already in regs)
        load_frag_a(af[1], sA, wm, lane, 1);
        load_frag_b(bf[1], sBs, wn, lane, 1);
#pragma unroll
        for (int i = 0; i < 4; i++)
#pragma unroll
            for (int j = 0; j < 8; j++)
                mma16816(acc[i][j], af[0][i], bf[0][j]);

        // ---- deferred: issue stage it+3 under the MMA shadow of ks1-ks3
        const int ls = it + STAGES - 1;
        if (ls < KIT) {
            const uint32_t st = sb + (uint32_t)(ls & (STAGES - 1)) * STAGE_BYTES;
            const size_t ko = (size_t)ls * (BK * 2);
#pragma unroll
            for (int p = 0; p < 4; p++)
                cp16(st + SW128((uint32_t)((rb + 32 * p) * 128 + chb)),
                     gAt + ko + (size_t)p * rstep);
#pragma unroll
            for (int p = 0; p < 8; p++)
                cp16(st + ABYTES + SW128((uint32_t)((rb + 32 * p) * 128 + chb)),
                     gBt + ko + (size_t)p * rstep);
        }
        CP_COMMIT();

        // ---- ks = 1..3
#pragma unroll
        for (int ks = 1; ks < 4; ks++) {
            const int cur = ks & 1, nxt = cur ^ 1;
            if (ks < 3) {
                load_frag_a(af[nxt], sA, wm, lane, ks + 1);
                load_frag_b(bf[nxt], sBs, wn, lane, ks + 1);
            } else if (it + 1 < KIT) {
                // prefetch ks=0 of NEXT stage (resident per CP_WAIT1 above)
                const uint32_t nA = sb + (uint32_t)((it + 1) & (STAGES - 1)) * STAGE_BYTES;
                load_frag_a(af[nxt], nA, wm, lane, 0);
                load_frag_b(bf[nxt], nA + ABYTES, wn, lane, 0);
            }
#pragma unroll
            for (int i = 0; i < 4; i++)
#pragma unroll
                for (int j = 0; j < 8; j++)
                    mma16816(acc[i][j], af[cur][i], bf[cur][j]);
        }
    }

    // ---------------- epilogue ----------------
    // frag (i,j): rows wm*64+i*16+lane/4 (+8), cols wn*64+j*8+2*(lane%4)
    const int rbase = wm * 64 + (lane >> 2);
    const int cbase = n0 + wn * 64 + 2 * (lane & 3);
    if (!F32OUT) {
        __half* Ch = (__half*)C;
#pragma unroll
        for (int i = 0; i < 4; i++) {
#pragma unroll
            for (int j = 0; j < 8; j++) {
                const int col = cbase + j * 8;
                const size_t r0 = (size_t)(m0 + rbase + i * 16) * LDC + col;
                const size_t r1 = r0 + (size_t)8 * LDC;
                *reinterpret_cast<__half2*>(Ch + r0) =
                    __floats2half2_rn(acc[i][j][0], acc[i][j][1]);
                *reinterpret_cast<__half2*>(Ch + r1) =
                    __floats2half2_rn(acc[i][j][2], acc[i][j][3]);
            }
        }
    } else {
        float* Cf = (float*)C;
#pragma unroll
        for (int i = 0; i < 4; i++) {
#pragma unroll
            for (int j = 0; j < 8; j++) {
                const int col = cbase + j * 8;
                const size_t r0 = (size_t)(m0 + rbase + i * 16) * LDC + col;
                const size_t r1 = r0 + (size_t)8 * LDC;
                *reinterpret_cast<float2*>(Cf + r0) =
                    make_float2(acc[i][j][0], acc[i][j][1]);
                *reinterpret_cast<float2*>(Cf + r1) =
                    make_float2(acc[i][j][2], acc[i][j][3]);
            }
        }
    }
}

// ---------------- launch ------------------------------------------------------
extern "C" void kernel_launch(void* const* d_in, const int* in_sizes, int n_in,
                              void* d_out, int out_size) {
    const float* x   = (const float*)d_in[0];
    const float* fc1 = (const float*)d_in[1];
    const float* fc2 = (const float*)d_in[2];
    const int*   nz  = (const int*)d_in[3];
    (void)in_sizes; (void)n_in; (void)out_size;

    void *pg, *pw1, *pw2, *ph, *pp;
    cudaGetSymbolAddress(&pg,  d_g);
    cudaGetSymbolAddress(&pw1, d_w1t);
    cudaGetSymbolAddress(&pw2, d_w2t);
    cudaGetSymbolAddress(&ph,  d_h);
    cudaGetSymbolAddress(&pp,  d_part);

    cudaFuncSetAttribute(gemm_f16<EMBED, EMBED, HIDDEN, false, false>,
                         cudaFuncAttributeMaxDynamicSharedMemorySize, SMEM_DYN);
    cudaFuncSetAttribute(gemm_f16<HIDDEN / 2, HIDDEN, OUTD, true, true>,
                         cudaFuncAttributeMaxDynamicSharedMemorySize, SMEM_DYN);

    // ---- fork: fc2 transpose runs on side stream, concurrent with everything
    // up to GEMM2 (it only reads fc2 / writes d_w2t). Capture-legal fork/join.
    cudaEventRecord(g_ov.e_fork, 0);
    cudaStreamWaitEvent(g_ov.s1, g_ov.e_fork, 0);
    transpose_convert<<<dim3(OUTD / 32, HIDDEN / 64), dim3(32, 8), 0, g_ov.s1>>>(
        fc2, (__half*)pw2, HIDDEN, OUTD);
    cudaEventRecord(g_ov.e_join, g_ov.s1);

    // ---- main stream: GEMM1 prerequisites + GEMM1
    build_map<<<1, 64>>>(nz);
    gather_convert<<<(MACT * (EMBED / 4)) / 256, 256>>>(x, nz, (__half*)pg);
    transpose_convert<<<dim3(HIDDEN / 32, EMBED / 64), dim3(32, 8)>>>(fc1, (__half*)pw1, EMBED, HIDDEN);

    gemm_f16<EMBED, EMBED, HIDDEN, false, false>
        <<<dim3(MACT / BM, HIDDEN / BN), 256, SMEM_DYN>>>(
            (const __half*)pg, (const __half*)pw1, ph);

    // ---- join: GEMM2 needs d_w2t
    cudaStreamWaitEvent(0, g_ov.e_join, 0);

    // GEMM2 split-K=2: partials = h @ fc2^T-layout (M=4096, N=4096, K=2x8192)
    gemm_f16<HIDDEN / 2, HIDDEN, OUTD, true, true>
        <<<dim3(MACT / BM, OUTD / BN, 2), 256, SMEM_DYN>>>(
            (const __half*)ph, (const __half*)pw2, pp);

    // full-output reduce: active = p0+p1, inactive = 0
    reduce_scatter_all<<<(64 * BLOCK * (OUTD / 4)) / 256, 256>>>(
        (const float*)pp, (float*)d_out);
}

// round 17
// speedup vs baseline: 1.0018x; 1.0018x over previous
#include <cuda_runtime.h>
#include <cuda_fp16.h>
#include <cstdint>
#include <cstddef>

// ---------------- problem dims (fixed by the dataset instance) ----------------
#define BLOCK   128
#define EMBED   4096
#define HIDDEN  16384
#define OUTD    4096
#define NZB     32
#define MACT    (NZB * BLOCK)   // 4096 active rows

// ---------------- scratch (device globals: allocation-free rule) -------------
__device__ __half d_g  [(size_t)MACT   * EMBED ];  // gathered activations fp16 [M,K]
__device__ __half d_w1t[(size_t)HIDDEN * EMBED ];  // fc1^T fp16 [N=HIDDEN, K=EMBED]
__device__ __half d_w2t[(size_t)OUTD   * HIDDEN];  // fc2^T fp16 [N=OUTD,   K=HIDDEN]
__device__ __half d_h  [(size_t)MACT   * HIDDEN];  // hidden fp16 [M,K2]
__device__ float  d_part[(size_t)2 * MACT * OUTD]; // GEMM2 split-K partials
__device__ int    d_map[64];                       // block -> active slot (-1 = inactive)

// ---- side stream + fork/join events: created ONCE at static-init (pre-capture,
// pre-checkpoint; no device allocation during kernel_launch itself) ------------
struct OverlapRes {
    cudaStream_t s1;
    cudaEvent_t  e_fork, e_join;
    OverlapRes() {
        cudaStreamCreateWithFlags(&s1, cudaStreamNonBlocking);
        cudaEventCreateWithFlags(&e_fork, cudaEventDisableTiming);
        cudaEventCreateWithFlags(&e_join, cudaEventDisableTiming);
    }
};
static OverlapRes g_ov;

// ---------------- PTX helpers (all portable, sm_80-level) ---------------------
__device__ __forceinline__ uint32_t smem_u32(const void* p) {
    uint32_t a;
    asm("{ .reg .u64 t; cvta.to.shared.u64 t, %1; cvt.u32.u64 %0, t; }" : "=r"(a) : "l"(p));
    return a;
}
__device__ __forceinline__ void cp16(uint32_t dst, const void* src) {
    asm volatile("cp.async.cg.shared.global [%0], [%1], 16;" :: "r"(dst), "l"(src) : "memory");
}
#define CP_COMMIT()  asm volatile("cp.async.commit_group;" ::: "memory")
#define CP_WAIT1()   asm volatile("cp.async.wait_group 1;" ::: "memory")
#define SW128(o) ((o) ^ (((o) >> 3) & 0x70))

__device__ __forceinline__ void ldsm_x4(uint32_t* r, uint32_t addr) {
    asm volatile("ldmatrix.sync.aligned.m8n8.x4.shared.b16 {%0,%1,%2,%3}, [%4];"
                 : "=r"(r[0]), "=r"(r[1]), "=r"(r[2]), "=r"(r[3]) : "r"(addr));
}
__device__ __forceinline__ void ldsm_x2(uint32_t* r, uint32_t addr) {
    asm volatile("ldmatrix.sync.aligned.m8n8.x2.shared.b16 {%0,%1}, [%2];"
                 : "=r"(r[0]), "=r"(r[1]) : "r"(addr));
}
__device__ __forceinline__ void mma16816(float* c, const uint32_t* a, const uint32_t* b) {
    asm volatile(
        "mma.sync.aligned.m16n8k16.row.col.f32.f16.f16.f32 "
        "{%0,%1,%2,%3}, {%4,%5,%6,%7}, {%8,%9}, {%0,%1,%2,%3};"
        : "+f"(c[0]), "+f"(c[1]), "+f"(c[2]), "+f"(c[3])
        : "r"(a[0]), "r"(a[1]), "r"(a[2]), "r"(a[3]), "r"(b[0]), "r"(b[1]));
}

// ---------------- conversion / plumbing kernels -------------------------------
__global__ void gather_convert(const float* __restrict__ x, const int* __restrict__ nz,
                               __half* __restrict__ g) {
    size_t idx  = (size_t)blockIdx.x * blockDim.x + threadIdx.x;  // over MACT*EMBED/4
    int    row  = (int)(idx >> 10);            // EMBED/4 = 1024 float4 per row
    int    col4 = (int)(idx & 1023);
    int    blk  = row >> 7;
    int    srow = nz[blk] * BLOCK + (row & 127);
    float4 v = reinterpret_cast<const float4*>(x)[(size_t)srow * (EMBED / 4) + col4];
    __half2* dst = reinterpret_cast<__half2*>(g + (size_t)row * EMBED + (size_t)col4 * 4);
    dst[0] = __floats2half2_rn(v.x, v.y);
    dst[1] = __floats2half2_rn(v.z, v.w);
}

// in [R,C] fp32 row-major -> out [C,R] fp16 row-major.
// 64(r) x 32(c) tile; writes are __half2 per lane -> full 128B transactions.
__global__ void transpose_convert(const float* __restrict__ in, __half* __restrict__ out,
                                  int R, int C) {
    __shared__ float tile[64][33];
    int c0 = blockIdx.x * 32, r0 = blockIdx.y * 64;
    int tx = threadIdx.x, ty = threadIdx.y;  // (32,8)
#pragma unroll
    for (int j = 0; j < 8; j++) {
        int row = ty + j * 8;                // 0..63
        tile[row][tx] = in[(size_t)(r0 + row) * C + c0 + tx];
    }
    __syncthreads();
#pragma unroll
    for (int i = 0; i < 4; i++) {
        int cc = ty + i * 8;                 // 0..31
        __half2 h = __floats2half2_rn(tile[2 * tx][cc], tile[2 * tx + 1][cc]);
        *reinterpret_cast<__half2*>(out + (size_t)(c0 + cc) * R + r0 + 2 * tx) = h;
    }
}

// block -> slot inverse map (single 64-thread block)
__global__ void build_map(const int* __restrict__ nz) {
    int t = threadIdx.x;
    if (t < 64) d_map[t] = -1;
    __syncthreads();
    if (t < 32) d_map[nz[t]] = t;
}

// full-output pass: active blocks = p0 + p1, inactive blocks = 0 (replaces memset)
__global__ void reduce_scatter_all(const float* __restrict__ part,
                                   float* __restrict__ out) {
    size_t idx  = (size_t)blockIdx.x * blockDim.x + threadIdx.x;  // over 8192*1024
    int    row  = (int)(idx >> 10);            // 0..8191
    int    col4 = (int)(idx & 1023);
    const int slot = d_map[row >> 7];
    float4 v = make_float4(0.f, 0.f, 0.f, 0.f);
    if (slot >= 0) {
        const int srow = slot * BLOCK + (row & 127);
        const float4* p0 = reinterpret_cast<const float4*>(part);
        const float4* p1 = p0 + (size_t)MACT * (OUTD / 4);
        const size_t o = (size_t)srow * (OUTD / 4) + col4;
        float4 a = p0[o], b = p1[o];
        v = make_float4(a.x + b.x, a.y + b.y, a.z + b.z, a.w + b.w);
    }
    reinterpret_cast<float4*>(out)[(size_t)row * (OUTD / 4) + col4] = v;
}

// ---------------- HMMA GEMM (R15, frozen) -------------------------------------
// C[m,n] = sum_k A[m,k]*B[n,k]; operands fp16 K-major with row stride LDA.
// CTA 128x256, warp tile 64x64 (8 warps, 2m x 4n), BK=64, 4-stage cp.async,
// m-fast grid; deferred next-stage issue (after ks0 MMAs). SPLITZ: blockIdx.z
// selects a K-half + a private fp32 partial plane (deterministic split-K).
constexpr int BM = 128, BN = 256, BK = 64, STAGES = 4;
constexpr uint32_t ABYTES      = BM * BK * 2;           // 16384
constexpr uint32_t BBYTES      = BN * BK * 2;           // 32768
constexpr uint32_t STAGE_BYTES = ABYTES + BBYTES;       // 49152
constexpr uint32_t SMEM_DYN    = STAGES * STAGE_BYTES;  // 196608

__device__ __forceinline__ void load_frag_a(uint32_t (&a)[4][4], uint32_t sA,
                                            int wm, int lane, int ks) {
#pragma unroll
    for (int i = 0; i < 4; i++) {
        const uint32_t r  = (uint32_t)(wm * 64 + i * 16 + (lane & 15));
        const uint32_t cb = (uint32_t)(ks * 32 + ((lane >> 4) << 4));
        ldsm_x4(a[i], sA + SW128(r * 128 + cb));
    }
}
__device__ __forceinline__ void load_frag_b(uint32_t (&b)[8][2], uint32_t sB,
                                            int wn, int lane, int ks) {
#pragma unroll
    for (int j = 0; j < 8; j++) {
        const uint32_t r  = (uint32_t)(wn * 64 + j * 8 + (lane & 7));
        const uint32_t cb = (uint32_t)(ks * 32 + (((lane >> 3) & 1) << 4));
        ldsm_x2(b[j], sB + SW128(r * 128 + cb));
    }
}

template <int KTOT, int LDA, int LDC, bool F32OUT, bool SPLITZ>
__global__ void __launch_bounds__(256, 1)
gemm_f16(const __half* __restrict__ A, const __half* __restrict__ B,
         void* __restrict__ C) {
    extern __shared__ char smem[];
    const uint32_t sb = smem_u32(smem);
    const int tid  = threadIdx.x;
    const int lane = tid & 31, wid = tid >> 5;
    const int wm = wid >> 2, wn = wid & 3;             // 2m x 4n warps, 64x64 tiles
    const int m0 = blockIdx.x * BM, n0 = blockIdx.y * BN;   // m-fast grid
    constexpr int KIT = KTOT / BK;

    if (SPLITZ) {                                      // K-half + partial plane
        const size_t koff = (size_t)blockIdx.z * KTOT;
        A += koff;  B += koff;
        C = (void*)((float*)C + (size_t)blockIdx.z * MACT * LDC);
    }

    // cp.async: stage = 384 rows x 128B (rows 0-127 = A, 128-383 = B).
    // thread t owns chunk (t&7) of rows (t>>3) + 32p; p 0-3 -> A, p 0-7 -> B.
    const int rb = tid >> 3;                 // base row 0..31
    const int chb = (tid & 7) * 16;          // byte chunk within 128B row
    const char* gAt = (const char*)(A + (size_t)(m0 + rb) * LDA) + chb;
    const char* gBt = (const char*)(B + (size_t)(n0 + rb) * LDA) + chb;
    const size_t rstep = (size_t)32 * LDA * 2;   // 32 rows in bytes

    float acc[4][8][4];
#pragma unroll
    for (int i = 0; i < 4; i++)
#pragma unroll
        for (int j = 0; j < 8; j++)
#pragma unroll
            for (int q = 0; q < 4; q++) acc[i][j][q] = 0.f;

    // prologue: fill stages 0..2 (3 commits)
#pragma unroll
    for (int s = 0; s < STAGES - 1; s++) {
        const uint32_t st = sb + (uint32_t)s * STAGE_BYTES;
        const size_t ko = (size_t)s * (BK * 2);
#pragma unroll
        for (int p = 0; p < 4; p++)
            cp16(st + SW128((uint32_t)((rb + 32 * p) * 128 + chb)),
                 gAt + ko + (size_t)p * rstep);
#pragma unroll
        for (int p = 0; p < 8; p++)
            cp16(st + ABYTES + SW128((uint32_t)((rb + 32 * p) * 128 + chb)),
                 gBt + ko + (size_t)p * rstep);
        CP_COMMIT();
    }

    uint32_t af[2][4][4], bf[2][8][2];   // double-buffered fragments

    for (int it = 0; it < KIT; it++) {
        // stages <= it+1 resident after this wait (3+it committed, <=1 pending)
        CP_WAIT1();
        __syncthreads();

        const uint32_t sA  = sb + (uint32_t)(it & (STAGES - 1)) * STAGE_BYTES;
        const uint32_t sBs = sA + ABYTES;

        if (it == 0) {             // prime buffer 0 (later iters arrive pre-loaded)
            load_frag_a(af[0], sA, wm, lane, 0);
            load_frag_b(bf[0], sBs, wn, lane, 0);
        }

        // ---- ks = 0: restart tensor pipe immediately (frags already in regs)
        load_frag_a(af[1], sA, wm, lane, 1);
        load_frag_b(bf[1], sBs, wn, lane, 1);
#pragma unroll
        for (int i = 0; i < 4; i++)
#pragma unroll
            for (int j = 0; j < 8; j++)
                mma16816(acc[i][j], af[0][i], bf[0][j]);

        // ---- deferred: issue stage it+3 under the MMA shadow of ks1-ks3
        const int ls = it + STAGES - 1;
        if (ls < KIT) {
            const uint32_t st = sb + (uint32_t)(ls & (STAGES - 1)) * STAGE_BYTES;
            const size_t ko = (size_t)ls * (BK * 2);
#pragma unroll
            for (int p = 0; p < 4; p++)
                cp16(st + SW128((uint32_t)((rb + 32 * p) * 128 + chb)),
                     gAt + ko + (size_t)p * rstep);
#pragma unroll
            for (int p = 0; p < 8; p++)
                cp16(st + ABYTES + SW128((uint32_t)((rb + 32 * p) * 128 + chb)),
                     gBt + ko + (size_t)p * rstep);
        }
        CP_COMMIT();

        // ---- ks = 1..3
#pragma unroll
        for (int ks = 1; ks < 4; ks++) {
            const int cur = ks & 1, nxt = cur ^ 1;
            if (ks < 3) {
                load_frag_a(af[nxt], sA, wm, lane, ks + 1);
                load_frag_b(bf[nxt], sBs, wn, lane, ks + 1);
            } else if (it + 1 < KIT) {
                // prefetch ks=0 of NEXT stage (resident per CP_WAIT1 above)
                const uint32_t nA = sb + (uint32_t)((it + 1) & (STAGES - 1)) * STAGE_BYTES;
                load_frag_a(af[nxt], nA, wm, lane, 0);
                load_frag_b(bf[nxt], nA + ABYTES, wn, lane, 0);
            }
#pragma unroll
            for (int i = 0; i < 4; i++)
#pragma unroll
                for (int j = 0; j < 8; j++)
                    mma16816(acc[i][j], af[cur][i], bf[cur][j]);
        }
    }

    // ---------------- epilogue ----------------
    // frag (i,j): rows wm*64+i*16+lane/4 (+8), cols wn*64+j*8+2*(lane%4)
    const int rbase = wm * 64 + (lane >> 2);
    const int cbase = n0 + wn * 64 + 2 * (lane & 3);
    if (!F32OUT) {
        __half* Ch = (__half*)C;
#pragma unroll
        for (int i = 0; i < 4; i++) {
#pragma unroll
            for (int j = 0; j < 8; j++) {
                const int col = cbase + j * 8;
                const size_t r0 = (size_t)(m0 + rbase + i * 16) * LDC + col;
                const size_t r1 = r0 + (size_t)8 * LDC;
                *reinterpret_cast<__half2*>(Ch + r0) =
                    __floats2half2_rn(acc[i][j][0], acc[i][j][1]);
                *reinterpret_cast<__half2*>(Ch + r1) =
                    __floats2half2_rn(acc[i][j][2], acc[i][j][3]);
            }
        }
    } else {
        float* Cf = (float*)C;
#pragma unroll
        for (int i = 0; i < 4; i++) {
#pragma unroll
            for (int j = 0; j < 8; j++) {
                const int col = cbase + j * 8;
                const size_t r0 = (size_t)(m0 + rbase + i * 16) * LDC + col;
                const size_t r1 = r0 + (size_t)8 * LDC;
                *reinterpret_cast<float2*>(Cf + r0) =
                    make_float2(acc[i][j][0], acc[i][j][1]);
                *reinterpret_cast<float2*>(Cf + r1) =
                    make_float2(acc[i][j][2], acc[i][j][3]);
            }
        }
    }
}

// ---------------- launch ------------------------------------------------------
extern "C" void kernel_launch(void* const* d_in, const int* in_sizes, int n_in,
                              void* d_out, int out_size) {
    const float* x   = (const float*)d_in[0];
    const float* fc1 = (const float*)d_in[1];
    const float* fc2 = (const float*)d_in[2];
    const int*   nz  = (const int*)d_in[3];
    (void)in_sizes; (void)n_in; (void)out_size;

    void *pg, *pw1, *pw2, *ph, *pp;
    cudaGetSymbolAddress(&pg,  d_g);
    cudaGetSymbolAddress(&pw1, d_w1t);
    cudaGetSymbolAddress(&pw2, d_w2t);
    cudaGetSymbolAddress(&ph,  d_h);
    cudaGetSymbolAddress(&pp,  d_part);

    cudaFuncSetAttribute(gemm_f16<EMBED, EMBED, HIDDEN, false, false>,
                         cudaFuncAttributeMaxDynamicSharedMemorySize, SMEM_DYN);
    cudaFuncSetAttribute(gemm_f16<HIDDEN / 2, HIDDEN, OUTD, true, true>,
                         cudaFuncAttributeMaxDynamicSharedMemorySize, SMEM_DYN);

    // ---- main stream: GEMM1 prerequisites (DRAM-bound phase, runs alone)
    build_map<<<1, 64>>>(nz);
    gather_convert<<<(MACT * (EMBED / 4)) / 256, 256>>>(x, nz, (__half*)pg);
    transpose_convert<<<dim3(HIDDEN / 32, EMBED / 64), dim3(32, 8)>>>(fc1, (__half*)pw1, EMBED, HIDDEN);

    // ---- fork AFTER the DRAM-bound plumbing: side stream waits for it, then
    // runs the fc2 transpose CONCURRENTLY WITH GEMM1 (tensor-bound, DRAM ~3%).
    cudaEventRecord(g_ov.e_fork, 0);
    cudaStreamWaitEvent(g_ov.s1, g_ov.e_fork, 0);
    transpose_convert<<<dim3(OUTD / 32, HIDDEN / 64), dim3(32, 8), 0, g_ov.s1>>>(
        fc2, (__half*)pw2, HIDDEN, OUTD);
    cudaEventRecord(g_ov.e_join, g_ov.s1);

    // GEMM1: h = g @ fc1^T-layout   (M=4096, N=16384, K=4096), m-fast grid
    gemm_f16<EMBED, EMBED, HIDDEN, false, false>
        <<<dim3(MACT / BM, HIDDEN / BN), 256, SMEM_DYN>>>(
            (const __half*)pg, (const __half*)pw1, ph);

    // ---- join: GEMM2 needs d_w2t
    cudaStreamWaitEvent(0, g_ov.e_join, 0);

    // GEMM2 split-K=2: partials = h @ fc2^T-layout (M=4096, N=4096, K=2x8192)
    gemm_f16<HIDDEN / 2, HIDDEN, OUTD, true, true>
        <<<dim3(MACT / BM, OUTD / BN, 2), 256, SMEM_DYN>>>(
            (const __half*)ph, (const __half*)pw2, pp);

    // full-output reduce: active = p0+p1, inactive = 0
    reduce_scatter_all<<<(64 * BLOCK * (OUTD / 4)) / 256, 256>>>(
        (const float*)pp, (float*)d_out);
}